// round 16
// baseline (speedup 1.0000x reference)
#include <cuda_runtime.h>
#include <cuda_fp16.h>
#include <math.h>
#include <stdint.h>

#define B_SZ 256
#define T_ENC 336
#define U_SZ 512
#define HORIZON 48

// ---------------- persistent device scratch ----------------
// W images (single fp16): [ntile 32][blob16 T16][64 n][16 k] blobs (2KB each)
__device__ __align__(256) __half g_We0h[32 * 36 * 1024];   // K=576 (x16|pad16|Wh512|pad32)
__device__ __align__(256) __half g_We1h[32 * 64 * 1024];   // K=1024
__device__ __align__(256) __half g_Wd0h[32 * 32 * 1024];   // K=512
__device__ __align__(256) __half g_Wd1h[32 * 64 * 1024];   // K=1024
// state images (fp16 hi + scaled lo): [mtile 4][blob16 32][64 m][16 k] per slot
#define SLOT_E 131072
__device__ __align__(256) __half g_o0h[(size_t)T_ENC * SLOT_E], g_o0l[(size_t)T_ENC * SLOT_E];
__device__ __align__(256) __half g_h1h[2 * SLOT_E], g_h1l[2 * SLOT_E];
__device__ __align__(256) __half g_d0h[2 * SLOT_E], g_d0l[2 * SLOT_E];
__device__ __align__(256) __half g_zh[SLOT_E], g_zl[SLOT_E];     // never written: zero
// encoder x images: per t: [mtile 4][2 blobs][64][16]; blob1 never written (zero)
__device__ __align__(256) __half g_xih[(size_t)T_ENC * 8192], g_xil[(size_t)T_ENC * 8192];
__device__ float g_c0[B_SZ * U_SZ], g_c1[B_SZ * U_SZ];
__device__ float g_biasp[4 * 2048], g_xrowp[2048], g_xb[2][B_SZ];

#define LO_SCALE 2048.0f
#define INV_LO_SCALE (1.0f / 2048.0f)

// fast-math activations
__device__ __forceinline__ float sig_f(float x) {
    x = fminf(fmaxf(x, -30.f), 30.f);
    return __fdividef(1.0f, 1.0f + __expf(-x));
}
__device__ __forceinline__ float tanh_f(float x) {
    float x2 = fminf(fmaxf(2.f * x, -30.f), 30.f);
    float e = __expf(x2);
    return __fdividef(e - 1.0f, e + 1.0f);
}

// ---------------- PTX helpers ----------------
__device__ __forceinline__ uint32_t smem_u32(const void* p) {
    uint32_t a;
    asm("{ .reg .u64 t; cvta.to.shared.u64 t, %1; cvt.u32.u64 %0, t; }" : "=r"(a) : "l"(p));
    return a;
}
__device__ __forceinline__ void cp16(uint32_t dst, const void* src) {
    asm volatile("cp.async.cg.shared.global [%0], [%1], 16;" :: "r"(dst), "l"(src) : "memory");
}
__device__ __forceinline__ void cp_commit() { asm volatile("cp.async.commit_group;" ::: "memory"); }
__device__ __forceinline__ void cp_wait(int rem) {
    if (rem <= 0)      asm volatile("cp.async.wait_group 0;" ::: "memory");
    else if (rem == 1) asm volatile("cp.async.wait_group 1;" ::: "memory");
    else               asm volatile("cp.async.wait_group 2;" ::: "memory");
}
__device__ __forceinline__ void ldmx4(uint32_t* r, uint32_t addr) {
    asm volatile("ldmatrix.sync.aligned.m8n8.x4.shared.b16 {%0,%1,%2,%3}, [%4];"
                 : "=r"(r[0]), "=r"(r[1]), "=r"(r[2]), "=r"(r[3]) : "r"(addr));
}
#define MMA(d, a, b0, b1)                                                          \
    asm volatile("mma.sync.aligned.m16n8k16.row.col.f32.f16.f16.f32 "              \
                 "{%0,%1,%2,%3}, {%4,%5,%6,%7}, {%8,%9}, {%0,%1,%2,%3};"           \
                 : "+f"(d[0]), "+f"(d[1]), "+f"(d[2]), "+f"(d[3])                  \
                 : "r"(a[0]), "r"(a[1]), "r"(a[2]), "r"(a[3]), "r"(b0), "r"(b1))

__device__ __forceinline__ uint32_t swz(uint32_t i) { return i ^ ((i >> 3) & 1); }

#define STAGE 24576     // Ah 8KB | Al' 8KB | W 8KB
#define NSTG 4
#define NTH 512

// ---------------------------------------------------------------------------
struct Job {
    const __half *a0h, *a0l;  int nk0;   // 16k blobs per mtile (seg0): hi + scaled-lo
    const __half *a1h, *a1l;  int nk1;   // seg1 (cb >= nk0+nk1 -> zeros)
    const __half *wh;         int T16;   // W image (single fp16), T16 mult of 4
    const float *biasp;
    const float *xrowp, *xvec, *bdp;     // dec-l0: rank-1 x, bd
    float *youtprev;                     // dec-l0: out col d-1 (stride 48)
    float *xinit;                        // dec-l0: x_{d+1} := bd0
    const float *projWd;                 // dec-l1: projection weights
    float *xnext;                        // dec-l1: atomicAdd target (= y_d)
    float *c;                            // cell state [B*U]
    __half *outh, *outl;                 // next-step h tile images (hi + scaled-lo)
};

// Fused LSTM step (HMMA fp16 2-product). Grid (32 ntiles, 4 mtiles, njobs),
// 512 threads (16 warps, warp-tile 16x16), 64-wide k chunks, 4-stage 96KB
// cp.async pipeline (prefetch 3), 2 CTAs/SM (occ 50%), one barrier per chunk.
__global__ __launch_bounds__(NTH, 2) void lstm_mma(Job j0, Job j1)
{
    extern __shared__ __align__(1024) unsigned char smem[];   // 98304
    const Job jb = (blockIdx.z == 0) ? j0 : j1;
    const uint32_t sb = smem_u32(smem);
    const int tid = threadIdx.x, lane = tid & 31, wid = tid >> 5;
    const int ntile = blockIdx.x, mtile = blockIdx.y;
    const int T64 = jb.T16 >> 2;

    // warp tile: 16 warps = 4 m x 4 n over the 64x64 block tile
    const int wm = wid & 3, wn = wid >> 2;
    const int arow = wm * 16 + (lane & 15);
    const int aseg = lane >> 4;
    const uint32_t offA = (uint32_t)((arow * 2 + (aseg ^ ((arow >> 2) & 1))) * 16);
    const int brow = wn * 16 + (lane & 7) + ((lane >> 4) << 3);
    const int bseg = (lane >> 3) & 1;
    const uint32_t offB = (uint32_t)((brow * 2 + (bseg ^ ((brow >> 2) & 1))) * 16);

    float accm[2][4];   // Ah * W  (2 n8 frags)
    float accc[2][4];   // Al' * W (scaled by 2^11)
#pragma unroll
    for (int jn = 0; jn < 2; ++jn)
#pragma unroll
        for (int q = 0; q < 4; ++q) { accm[jn][q] = 0.f; accc[jn][q] = 0.f; }

    // load one 64-k chunk: 1536 16B-units (Ah 512 | Al 512 | W 512); 3 per thread
    auto load_chunk = [&](int t64) {
        uint32_t dstb = sb + (uint32_t)(t64 % NSTG) * STAGE;
#pragma unroll
        for (int r = 0; r < 3; ++r) {
            int u = tid + NTH * r;             // 0..1535
            int region = u >> 9;               // 0 Ah, 1 Al', 2 W
            int sub = (u >> 7) & 3;            // blob within chunk
            int jj = u & 127;
            int cb = 4 * t64 + sub;            // 16k blob index
            const __half* src;
            if (region < 2) {
                if (cb < jb.nk0)
                    src = ((region == 0) ? jb.a0h : jb.a0l) + ((size_t)mtile * jb.nk0 + cb) * 1024;
                else if (cb < jb.nk0 + jb.nk1)
                    src = ((region == 0) ? jb.a1h : jb.a1l) + ((size_t)mtile * jb.nk1 + (cb - jb.nk0)) * 1024;
                else
                    src = (region == 0) ? g_zh : g_zl;    // zero padding
            } else {
                src = jb.wh + ((size_t)ntile * jb.T16 + cb) * 1024;
            }
            cp16(dstb + (uint32_t)(region * 8192 + sub * 2048) + swz((uint32_t)jj) * 16,
                 src + jj * 8);
        }
        cp_commit();
    };

    load_chunk(0); load_chunk(1); load_chunk(2);

    for (int t = 0; t < T64; ++t) {
        int rem = T64 - 1 - t; if (rem > 2) rem = 2;
        cp_wait(rem);
        __syncthreads();                        // single barrier per chunk
        if (t + 3 < T64) load_chunk(t + 3);     // writes slot (t-1)%4, drained above
        uint32_t s = sb + (uint32_t)(t % NSTG) * STAGE;
#pragma unroll
        for (int ks = 0; ks < 4; ++ks) {
            uint32_t s2 = s + (uint32_t)ks * 2048;
            uint32_t ah[4], al[4], w[4];
            ldmx4(ah, s2 + offA);
            ldmx4(al, s2 + 8192 + offA);
            ldmx4(w, s2 + 16384 + offB);
#pragma unroll
            for (int jn = 0; jn < 2; ++jn) {
                MMA(accm[jn], ah, w[2 * jn], w[2 * jn + 1]);
                MMA(accc[jn], al, w[2 * jn], w[2 * jn + 1]);
            }
        }
    }
    __syncthreads();   // all warps done reading stages before Z aliases smem

    // ---- epilogue: combine accumulators -> smem z-tile (alias stage buffers) ----
    float* Z = (float*)smem;                 // [64][68]
    const int g = lane >> 2, cc2 = (lane & 3) * 2;
#pragma unroll
    for (int jn = 0; jn < 2; ++jn) {
        int r0 = wm * 16 + g;
        int c0 = wn * 16 + jn * 8 + cc2;
        Z[r0 * 68 + c0]           = accm[jn][0] + accc[jn][0] * INV_LO_SCALE;
        Z[r0 * 68 + c0 + 1]       = accm[jn][1] + accc[jn][1] * INV_LO_SCALE;
        Z[(r0 + 8) * 68 + c0]     = accm[jn][2] + accc[jn][2] * INV_LO_SCALE;
        Z[(r0 + 8) * 68 + c0 + 1] = accm[jn][3] + accc[jn][3] * INV_LO_SCALE;
    }
    __syncthreads();

    const float bd0 = jb.bdp ? jb.bdp[0] : 0.f;

#pragma unroll
    for (int q = 0; q < 2; ++q) {
        int idx = tid + NTH * q;
        int m_loc = idx >> 4, uo = idx & 15;
        int m = mtile * 64 + m_loc;
        int pbase = ntile * 64 + uo;
        float zi = Z[m_loc * 68 + uo]       + jb.biasp[pbase];
        float zf = Z[m_loc * 68 + 16 + uo]  + jb.biasp[pbase + 16];
        float zg = Z[m_loc * 68 + 32 + uo]  + jb.biasp[pbase + 32];
        float zo = Z[m_loc * 68 + 48 + uo]  + jb.biasp[pbase + 48];
        float xm = 0.f;
        if (jb.xrowp) {
            xm = jb.xvec[m];
            zi += xm * jb.xrowp[pbase];
            zf += xm * jb.xrowp[pbase + 16];
            zg += xm * jb.xrowp[pbase + 32];
            zo += xm * jb.xrowp[pbase + 48];
        }
        float ig = sig_f(zi), fg = sig_f(zf), gg = tanh_f(zg), og = sig_f(zo);
        int u = ntile * 16 + uo;
        int ci = m * U_SZ + u;
        float cn = fg * jb.c[ci] + ig * gg;
        jb.c[ci] = cn;
        float h = og * tanh_f(cn);
        __half hh = __float2half_rn(h);
        __half hl = __float2half_rn((h - __half2float(hh)) * LO_SCALE);
        size_t off = (((size_t)mtile * 32 + ntile) * 64 + m_loc) * 16 + uo;
        jb.outh[off] = hh;
        jb.outl[off] = hl;

        if (jb.xrowp && uo == 0 && ntile == 0) {
            if (jb.youtprev) jb.youtprev[m * HORIZON] = xm;   // out col d-1 = y_{d-1}
            jb.xinit[m] = bd0;                                 // seed next-x accumulator
        }
        if (jb.projWd) {
            float p = h * jb.projWd[u];
            p += __shfl_xor_sync(0xffffffffu, p, 8, 16);
            p += __shfl_xor_sync(0xffffffffu, p, 4, 16);
            p += __shfl_xor_sync(0xffffffffu, p, 2, 16);
            p += __shfl_xor_sync(0xffffffffu, p, 1, 16);
            if (uo == 0) atomicAdd(&jb.xnext[m], p);
        }
    }
}

// ---------------- preprocessing (2 launches) ----------------
__device__ __forceinline__ void w_emit(const float* Wx, int kx, const float* Wh, int whs,
                                       int khi, int T16, __half* dh, int i)
{
    int k = i >> 11, orig = i & 2047;
    int gate = orig >> 9, rem = orig & 511;
    int ntile = rem >> 4, uo = rem & 15;
    int nloc = gate * 16 + uo;
    float w = 0.f;
    if (k < kx)                    w = Wx[(size_t)k * 2048 + orig];
    else if (k >= whs && k < khi)  w = Wh[(size_t)(k - whs) * 2048 + orig];
    size_t off = (((size_t)ntile * T16 + (k >> 4)) * 64 + nloc) * 16 + (k & 15);
    dh[off] = __float2half_rn(w);
}

__global__ void prep_w(const float* eWx0, const float* eWh0,
                       const float* eWx1, const float* eWh1,
                       const float* dWh0,
                       const float* dWx1, const float* dWh1)
{
    int i = blockIdx.x * 256 + threadIdx.x;
    const int E0 = 576 * 2048, E1 = 1024 * 2048, E2 = 512 * 2048, E3 = 1024 * 2048;
    if (i < E0)                     w_emit(eWx0, 16, eWh0, 32, 544, 36, g_We0h, i);
    else if (i < E0 + E1)           w_emit(eWx1, 512, eWh1, 512, 1024, 64, g_We1h, i - E0);
    else if (i < E0 + E1 + E2)      w_emit(nullptr, 0, dWh0, 0, 512, 32, g_Wd0h, i - E0 - E1);
    else if (i < E0 + E1 + E2 + E3) w_emit(dWx1, 512, dWh1, 512, 1024, 64, g_Wd1h, i - E0 - E1 - E2);
}

__global__ void prep_misc(const float* __restrict__ enc, const float* __restrict__ dcin,
                          const float* __restrict__ b0, const float* __restrict__ b1,
                          const float* __restrict__ b2, const float* __restrict__ b3,
                          const float* __restrict__ dWx0)
{
    int i = blockIdx.x * 256 + threadIdx.x;
    if (i < T_ENC * B_SZ * 16) {
        int t = i >> 12, r = i & 4095, m = r >> 4, k = r & 15;
        float v = enc[(size_t)m * (T_ENC * 16) + t * 16 + k];
        __half h = __float2half_rn(v);
        __half l = __float2half_rn((v - __half2float(h)) * LO_SCALE);
        size_t off = (((size_t)t * 4 + (m >> 6)) * 2) * 1024 + (size_t)(m & 63) * 16 + k;
        g_xih[off] = h;
        g_xil[off] = l;
    }
    if (i < 5 * 2048) {
        int g = i >> 11, pcol = i & 2047;
        int orig = ((pcol >> 4) & 3) * 512 + (pcol >> 6) * 16 + (pcol & 15);
        if (g == 4) g_xrowp[pcol] = dWx0[orig];
        else {
            const float* s = (g == 0) ? b0 : (g == 1) ? b1 : (g == 2) ? b2 : b3;
            g_biasp[g * 2048 + pcol] = s[orig];
        }
    }
    if (i < B_SZ * U_SZ) { g_c0[i] = 0.f; g_c1[i] = 0.f; }
    if (i < B_SZ) g_xb[0][i] = dcin[i];
}

__global__ void final_kernel(float* __restrict__ out)
{
    int m = threadIdx.x;
    if (m < B_SZ) out[m * HORIZON + (HORIZON - 1)] = g_xb[HORIZON & 1][m];
}

extern "C" void kernel_launch(void* const* d_in, const int* in_sizes, int n_in,
                              void* d_out, int out_size)
{
    const float* enc  = (const float*)d_in[0];
    const float* dcin = (const float*)d_in[1];
    const float* eWx0 = (const float*)d_in[2];
    const float* eWh0 = (const float*)d_in[3];
    const float* eb0  = (const float*)d_in[4];
    const float* eWx1 = (const float*)d_in[5];
    const float* eWh1 = (const float*)d_in[6];
    const float* eb1  = (const float*)d_in[7];
    const float* dWx0 = (const float*)d_in[8];
    const float* dWh0 = (const float*)d_in[9];
    const float* db0  = (const float*)d_in[10];
    const float* dWx1 = (const float*)d_in[11];
    const float* dWh1 = (const float*)d_in[12];
    const float* db1  = (const float*)d_in[13];
    const float* Wd   = (const float*)d_in[14];
    const float* bd   = (const float*)d_in[15];
    float* out = (float*)d_out;

    cudaFuncSetAttribute(lstm_mma, cudaFuncAttributeMaxDynamicSharedMemorySize, NSTG * STAGE);

    __half *We0h, *We1h, *Wd0h, *Wd1h;
    __half *o0h, *o0l, *xih, *xil, *h1h, *h1l, *d0h, *d0l, *zh, *zl;
    float *c0, *c1, *biasp, *xrowp, *xb;
    cudaGetSymbolAddress((void**)&We0h, g_We0h);
    cudaGetSymbolAddress((void**)&We1h, g_We1h);
    cudaGetSymbolAddress((void**)&Wd0h, g_Wd0h);
    cudaGetSymbolAddress((void**)&Wd1h, g_Wd1h);
    cudaGetSymbolAddress((void**)&o0h, g_o0h);   cudaGetSymbolAddress((void**)&o0l, g_o0l);
    cudaGetSymbolAddress((void**)&xih, g_xih);   cudaGetSymbolAddress((void**)&xil, g_xil);
    cudaGetSymbolAddress((void**)&h1h, g_h1h);   cudaGetSymbolAddress((void**)&h1l, g_h1l);
    cudaGetSymbolAddress((void**)&d0h, g_d0h);   cudaGetSymbolAddress((void**)&d0l, g_d0l);
    cudaGetSymbolAddress((void**)&zh, g_zh);     cudaGetSymbolAddress((void**)&zl, g_zl);
    cudaGetSymbolAddress((void**)&c0, g_c0);     cudaGetSymbolAddress((void**)&c1, g_c1);
    cudaGetSymbolAddress((void**)&biasp, g_biasp);
    cudaGetSymbolAddress((void**)&xrowp, g_xrowp);
    cudaGetSymbolAddress((void**)&xb, g_xb);

    auto mkjob = [&](const __half* a0hh, const __half* a0ll, int nk0,
                     const __half* a1hh, const __half* a1ll, int nk1,
                     const __half* whh, int T16,
                     const float* bp, float* cst,
                     __half* oh, __half* ol) {
        Job j;
        j.a0h = a0hh; j.a0l = a0ll; j.nk0 = nk0;
        j.a1h = a1hh; j.a1l = a1ll; j.nk1 = nk1;
        j.wh = whh; j.T16 = T16;
        j.biasp = bp;
        j.xrowp = nullptr; j.xvec = nullptr; j.bdp = nullptr;
        j.youtprev = nullptr; j.xinit = nullptr;
        j.projWd = nullptr; j.xnext = nullptr;
        j.c = cst; j.outh = oh; j.outl = ol;
        return j;
    };

    // ---- preprocessing ----
    const int WTOT = (576 + 1024 + 512 + 1024) * 2048;
    prep_w<<<(WTOT + 255) / 256, 256>>>(eWx0, eWh0, eWx1, eWh1, dWh0, dWx1, dWh1);
    prep_misc<<<(T_ENC * B_SZ * 16 + 255) / 256, 256>>>(enc, dcin, eb0, eb1, db0, db1, dWx0);

    // ---- encoder: fused l0(s) + l1(s-1), s = 0..336 ----
    for (int s = 0; s <= T_ENC; ++s) {
        Job jobs[2];
        int nj = 0;
        if (s < T_ENC) {   // layer0 step s (T16=36: x2 | h32 | zero-pad2)
            const __half* hh = (s == 0) ? zh : o0h + (size_t)(s - 1) * SLOT_E;
            const __half* hl = (s == 0) ? zl : o0l + (size_t)(s - 1) * SLOT_E;
            jobs[nj++] = mkjob(xih + (size_t)s * 8192, xil + (size_t)s * 8192, 2,
                               hh, hl, 32, We0h, 36,
                               biasp + 0 * 2048, c0,
                               o0h + (size_t)s * SLOT_E, o0l + (size_t)s * SLOT_E);
        }
        if (s >= 1) {      // layer1 step s-1
            int t = s - 1;
            const __half* hh = (t == 0) ? zh : h1h + (size_t)(t & 1) * SLOT_E;
            const __half* hl = (t == 0) ? zl : h1l + (size_t)(t & 1) * SLOT_E;
            jobs[nj++] = mkjob(o0h + (size_t)t * SLOT_E, o0l + (size_t)t * SLOT_E, 32,
                               hh, hl, 32, We1h, 64,
                               biasp + 1 * 2048, c1,
                               h1h + (size_t)((t + 1) & 1) * SLOT_E,
                               h1l + (size_t)((t + 1) & 1) * SLOT_E);
        }
        dim3 grid(32, 4, nj);
        lstm_mma<<<grid, NTH, NSTG * STAGE>>>(jobs[0], jobs[nj - 1]);
    }

    // ---- decoder ----
    for (int d = 0; d < HORIZON; ++d) {
        // layer 0 (K=512) + rank-1 x + bookkeeping
        {
            const __half* h0hh = (d == 0) ? o0h + (size_t)(T_ENC - 1) * SLOT_E
                                          : d0h + (size_t)(d & 1) * SLOT_E;
            const __half* h0ll = (d == 0) ? o0l + (size_t)(T_ENC - 1) * SLOT_E
                                          : d0l + (size_t)(d & 1) * SLOT_E;
            Job j = mkjob(h0hh, h0ll, 32, nullptr, nullptr, 0,
                          Wd0h, 32, biasp + 2 * 2048, c0,
                          d0h + (size_t)((d & 1) ^ 1) * SLOT_E,
                          d0l + (size_t)((d & 1) ^ 1) * SLOT_E);
            j.xrowp = xrowp;
            j.xvec  = xb + (size_t)(d & 1) * B_SZ;
            j.bdp   = bd;
            j.youtprev = (d == 0) ? nullptr : out + (d - 1);
            j.xinit = xb + (size_t)((d + 1) & 1) * B_SZ;
            lstm_mma<<<dim3(32, 4, 1), NTH, NSTG * STAGE>>>(j, j);
        }
        // layer 1 (K=1024) + fused projection
        {
            Job j = mkjob(d0h + (size_t)((d & 1) ^ 1) * SLOT_E,
                          d0l + (size_t)((d & 1) ^ 1) * SLOT_E, 32,
                          h1h + (size_t)(d & 1) * SLOT_E,
                          h1l + (size_t)(d & 1) * SLOT_E, 32,
                          Wd1h, 64, biasp + 3 * 2048, c1,
                          h1h + (size_t)((d + 1) & 1) * SLOT_E,
                          h1l + (size_t)((d + 1) & 1) * SLOT_E);
            j.projWd = Wd;
            j.xnext  = xb + (size_t)((d + 1) & 1) * B_SZ;
            lstm_mma<<<dim3(32, 4, 1), NTH, NSTG * STAGE>>>(j, j);
        }
    }
    final_kernel<<<1, 256>>>(out);
}

// round 17
// speedup vs baseline: 1.6905x; 1.6905x over previous
#include <cuda_runtime.h>
#include <cuda_fp16.h>
#include <math.h>
#include <stdint.h>

#define B_SZ 256
#define T_ENC 336
#define U_SZ 512
#define HORIZON 48

// ---------------- persistent device scratch ----------------
// W images (single fp16): [ntile 32][blob16 T16][64 n][16 k] blobs (2KB each)
__device__ __align__(256) __half g_We0h[32 * 36 * 1024];   // K=576 (x16|pad16|Wh512|pad32)
__device__ __align__(256) __half g_We1h[32 * 64 * 1024];   // K=1024
__device__ __align__(256) __half g_Wd0h[32 * 32 * 1024];   // K=512
__device__ __align__(256) __half g_Wd1h[32 * 64 * 1024];   // K=1024
// state images (single fp16): [mtile 4][blob16 32][64 m][16 k] per slot
#define SLOT_E 131072
__device__ __align__(256) __half g_o0h[(size_t)T_ENC * SLOT_E];
__device__ __align__(256) __half g_h1h[2 * SLOT_E];
__device__ __align__(256) __half g_d0h[2 * SLOT_E];
__device__ __align__(256) __half g_zh[SLOT_E];             // never written: zero
// encoder x images: per t: [mtile 4][2 blobs][64][16]; blob1 never written (zero)
__device__ __align__(256) __half g_xih[(size_t)T_ENC * 8192];
__device__ float g_c0[B_SZ * U_SZ], g_c1[B_SZ * U_SZ];
__device__ float g_biasp[4 * 2048], g_xrowp[2048], g_xb[2][B_SZ];

// fast-math activations
__device__ __forceinline__ float sig_f(float x) {
    x = fminf(fmaxf(x, -30.f), 30.f);
    return __fdividef(1.0f, 1.0f + __expf(-x));
}
__device__ __forceinline__ float tanh_f(float x) {
    float x2 = fminf(fmaxf(2.f * x, -30.f), 30.f);
    float e = __expf(x2);
    return __fdividef(e - 1.0f, e + 1.0f);
}

// ---------------- PTX helpers ----------------
__device__ __forceinline__ uint32_t smem_u32(const void* p) {
    uint32_t a;
    asm("{ .reg .u64 t; cvta.to.shared.u64 t, %1; cvt.u32.u64 %0, t; }" : "=r"(a) : "l"(p));
    return a;
}
__device__ __forceinline__ void cp16(uint32_t dst, const void* src) {
    asm volatile("cp.async.cg.shared.global [%0], [%1], 16;" :: "r"(dst), "l"(src) : "memory");
}
__device__ __forceinline__ void cp_commit() { asm volatile("cp.async.commit_group;" ::: "memory"); }
__device__ __forceinline__ void cp_wait(int rem) {
    if (rem <= 0)      asm volatile("cp.async.wait_group 0;" ::: "memory");
    else if (rem == 1) asm volatile("cp.async.wait_group 1;" ::: "memory");
    else               asm volatile("cp.async.wait_group 2;" ::: "memory");
}
__device__ __forceinline__ void ldmx4(uint32_t* r, uint32_t addr) {
    asm volatile("ldmatrix.sync.aligned.m8n8.x4.shared.b16 {%0,%1,%2,%3}, [%4];"
                 : "=r"(r[0]), "=r"(r[1]), "=r"(r[2]), "=r"(r[3]) : "r"(addr));
}
#define MMA(d, a, b0, b1)                                                          \
    asm volatile("mma.sync.aligned.m16n8k16.row.col.f32.f16.f16.f32 "              \
                 "{%0,%1,%2,%3}, {%4,%5,%6,%7}, {%8,%9}, {%0,%1,%2,%3};"           \
                 : "+f"(d[0]), "+f"(d[1]), "+f"(d[2]), "+f"(d[3])                  \
                 : "r"(a[0]), "r"(a[1]), "r"(a[2]), "r"(a[3]), "r"(b0), "r"(b1))

__device__ __forceinline__ uint32_t swz(uint32_t i) { return i ^ ((i >> 3) & 1); }

#define STAGE 16384     // A 8KB | W 8KB
#define NSTG 4

// ---------------------------------------------------------------------------
struct Job {
    const __half *a0h;  int nk0;   // 16k blobs per mtile (seg0)
    const __half *a1h;  int nk1;   // seg1 (cb >= nk0+nk1 -> zeros)
    const __half *wh;   int T16;   // W image (single fp16), T16 mult of 4
    const float *biasp;
    const float *xrowp, *xvec, *bdp;     // dec-l0: rank-1 x, bd
    float *youtprev;                     // dec-l0: out col d-1 (stride 48)
    float *xinit;                        // dec-l0: x_{d+1} := bd0
    const float *projWd;                 // dec-l1: projection weights
    float *xnext;                        // dec-l1: atomicAdd target (= y_d)
    float *c;                            // cell state [B*U]
    __half *outh;                        // next-step h tile image
};

// Fused LSTM step (HMMA fp16 single-product). Grid (32 ntiles, 4 mtiles, njobs),
// 256 threads (8 warps, warp-tile 32x16), 64-wide k chunks, 4-stage 64KB
// cp.async pipeline (prefetch 3), 2 CTAs/SM, one barrier per chunk.
__global__ __launch_bounds__(256, 2) void lstm_mma(Job j0, Job j1)
{
    extern __shared__ __align__(1024) unsigned char smem[];   // 65536
    const Job jb = (blockIdx.z == 0) ? j0 : j1;
    const uint32_t sb = smem_u32(smem);
    const int tid = threadIdx.x, lane = tid & 31, wid = tid >> 5;
    const int ntile = blockIdx.x, mtile = blockIdx.y;
    const int T64 = jb.T16 >> 2;

    // ldmatrix offsets (blob-local, 2KB blobs of [64][16] fp16)
    const int wm = wid & 1, wn = wid >> 1;
    const int arow = wm * 32 + (lane & 15);
    const int aseg = lane >> 4;
    const uint32_t offA0 = (uint32_t)((arow * 2 + (aseg ^ ((arow >> 2) & 1))) * 16);
    const int arow1 = arow + 16;
    const uint32_t offA1 = (uint32_t)((arow1 * 2 + (aseg ^ ((arow1 >> 2) & 1))) * 16);
    const int brow = wn * 16 + (lane & 7) + ((lane >> 4) << 3);
    const int bseg = (lane >> 3) & 1;
    const uint32_t offB = (uint32_t)((brow * 2 + (bseg ^ ((brow >> 2) & 1))) * 16);

    float acc[2][2][4];
#pragma unroll
    for (int im = 0; im < 2; ++im)
#pragma unroll
        for (int jn = 0; jn < 2; ++jn)
#pragma unroll
            for (int q = 0; q < 4; ++q) acc[im][jn][q] = 0.f;

    // load one 64-k chunk: 1024 16B-units (A 512 | W 512); 4 per thread
    auto load_chunk = [&](int t64) {
        uint32_t dstb = sb + (uint32_t)(t64 % NSTG) * STAGE;
#pragma unroll
        for (int r = 0; r < 4; ++r) {
            int u = tid + 256 * r;             // 0..1023
            int region = u >> 9;               // 0 A, 1 W
            int sub = (u >> 7) & 3;            // blob within chunk
            int jj = u & 127;
            int cb = 4 * t64 + sub;            // 16k blob index
            const __half* src;
            if (region == 0) {
                if (cb < jb.nk0)
                    src = jb.a0h + ((size_t)mtile * jb.nk0 + cb) * 1024;
                else if (cb < jb.nk0 + jb.nk1)
                    src = jb.a1h + ((size_t)mtile * jb.nk1 + (cb - jb.nk0)) * 1024;
                else
                    src = g_zh;                // zero padding
            } else {
                src = jb.wh + ((size_t)ntile * jb.T16 + cb) * 1024;
            }
            cp16(dstb + (uint32_t)(region * 8192 + sub * 2048) + swz((uint32_t)jj) * 16,
                 src + jj * 8);
        }
        cp_commit();
    };

    load_chunk(0); load_chunk(1); load_chunk(2);

    for (int t = 0; t < T64; ++t) {
        int rem = T64 - 1 - t; if (rem > 2) rem = 2;
        cp_wait(rem);
        __syncthreads();                        // single barrier per chunk
        if (t + 3 < T64) load_chunk(t + 3);     // writes slot (t-1)%4, drained above
        uint32_t s = sb + (uint32_t)(t % NSTG) * STAGE;
#pragma unroll
        for (int ks = 0; ks < 4; ++ks) {
            uint32_t s2 = s + (uint32_t)ks * 2048;
            uint32_t ah0[4], ah1[4], w[4];
            ldmx4(ah0, s2 + offA0);
            ldmx4(ah1, s2 + offA1);
            ldmx4(w, s2 + 8192 + offB);
#pragma unroll
            for (int jn = 0; jn < 2; ++jn) {
                MMA(acc[0][jn], ah0, w[2 * jn], w[2 * jn + 1]);
                MMA(acc[1][jn], ah1, w[2 * jn], w[2 * jn + 1]);
            }
        }
    }
    __syncthreads();   // all warps done reading stages before Z aliases smem

    // ---- epilogue: accum frags -> smem z-tile (alias stage buffers) ----
    float* Z = (float*)smem;                 // [64][68]
    const int g = lane >> 2, cc2 = (lane & 3) * 2;
#pragma unroll
    for (int im = 0; im < 2; ++im)
#pragma unroll
        for (int jn = 0; jn < 2; ++jn) {
            int r0 = wm * 32 + im * 16 + g;
            int c0 = wn * 16 + jn * 8 + cc2;
            Z[r0 * 68 + c0]           = acc[im][jn][0];
            Z[r0 * 68 + c0 + 1]       = acc[im][jn][1];
            Z[(r0 + 8) * 68 + c0]     = acc[im][jn][2];
            Z[(r0 + 8) * 68 + c0 + 1] = acc[im][jn][3];
        }
    __syncthreads();

    const float bd0 = jb.bdp ? jb.bdp[0] : 0.f;

#pragma unroll
    for (int q = 0; q < 4; ++q) {
        int idx = tid + 256 * q;
        int m_loc = idx >> 4, uo = idx & 15;
        int m = mtile * 64 + m_loc;
        int pbase = ntile * 64 + uo;
        float zi = Z[m_loc * 68 + uo]       + jb.biasp[pbase];
        float zf = Z[m_loc * 68 + 16 + uo]  + jb.biasp[pbase + 16];
        float zg = Z[m_loc * 68 + 32 + uo]  + jb.biasp[pbase + 32];
        float zo = Z[m_loc * 68 + 48 + uo]  + jb.biasp[pbase + 48];
        float xm = 0.f;
        if (jb.xrowp) {
            xm = jb.xvec[m];
            zi += xm * jb.xrowp[pbase];
            zf += xm * jb.xrowp[pbase + 16];
            zg += xm * jb.xrowp[pbase + 32];
            zo += xm * jb.xrowp[pbase + 48];
        }
        float ig = sig_f(zi), fg = sig_f(zf), gg = tanh_f(zg), og = sig_f(zo);
        int u = ntile * 16 + uo;
        int ci = m * U_SZ + u;
        float cn = fg * jb.c[ci] + ig * gg;
        jb.c[ci] = cn;
        float h = og * tanh_f(cn);
        size_t off = (((size_t)mtile * 32 + ntile) * 64 + m_loc) * 16 + uo;
        jb.outh[off] = __float2half_rn(h);

        if (jb.xrowp && uo == 0 && ntile == 0) {
            if (jb.youtprev) jb.youtprev[m * HORIZON] = xm;   // out col d-1 = y_{d-1}
            jb.xinit[m] = bd0;                                 // seed next-x accumulator
        }
        if (jb.projWd) {
            float p = h * jb.projWd[u];
            p += __shfl_xor_sync(0xffffffffu, p, 8, 16);
            p += __shfl_xor_sync(0xffffffffu, p, 4, 16);
            p += __shfl_xor_sync(0xffffffffu, p, 2, 16);
            p += __shfl_xor_sync(0xffffffffu, p, 1, 16);
            if (uo == 0) atomicAdd(&jb.xnext[m], p);
        }
    }
}

// ---------------- preprocessing (2 launches) ----------------
__device__ __forceinline__ void w_emit(const float* Wx, int kx, const float* Wh, int whs,
                                       int khi, int T16, __half* dh, int i)
{
    int k = i >> 11, orig = i & 2047;
    int gate = orig >> 9, rem = orig & 511;
    int ntile = rem >> 4, uo = rem & 15;
    int nloc = gate * 16 + uo;
    float w = 0.f;
    if (k < kx)                    w = Wx[(size_t)k * 2048 + orig];
    else if (k >= whs && k < khi)  w = Wh[(size_t)(k - whs) * 2048 + orig];
    size_t off = (((size_t)ntile * T16 + (k >> 4)) * 64 + nloc) * 16 + (k & 15);
    dh[off] = __float2half_rn(w);
}

__global__ void prep_w(const float* eWx0, const float* eWh0,
                       const float* eWx1, const float* eWh1,
                       const float* dWh0,
                       const float* dWx1, const float* dWh1)
{
    int i = blockIdx.x * 256 + threadIdx.x;
    const int E0 = 576 * 2048, E1 = 1024 * 2048, E2 = 512 * 2048, E3 = 1024 * 2048;
    if (i < E0)                     w_emit(eWx0, 16, eWh0, 32, 544, 36, g_We0h, i);
    else if (i < E0 + E1)           w_emit(eWx1, 512, eWh1, 512, 1024, 64, g_We1h, i - E0);
    else if (i < E0 + E1 + E2)      w_emit(nullptr, 0, dWh0, 0, 512, 32, g_Wd0h, i - E0 - E1);
    else if (i < E0 + E1 + E2 + E3) w_emit(dWx1, 512, dWh1, 512, 1024, 64, g_Wd1h, i - E0 - E1 - E2);
}

__global__ void prep_misc(const float* __restrict__ enc, const float* __restrict__ dcin,
                          const float* __restrict__ b0, const float* __restrict__ b1,
                          const float* __restrict__ b2, const float* __restrict__ b3,
                          const float* __restrict__ dWx0)
{
    int i = blockIdx.x * 256 + threadIdx.x;
    if (i < T_ENC * B_SZ * 16) {
        int t = i >> 12, r = i & 4095, m = r >> 4, k = r & 15;
        float v = enc[(size_t)m * (T_ENC * 16) + t * 16 + k];
        size_t off = (((size_t)t * 4 + (m >> 6)) * 2) * 1024 + (size_t)(m & 63) * 16 + k;
        g_xih[off] = __float2half_rn(v);
    }
    if (i < 5 * 2048) {
        int g = i >> 11, pcol = i & 2047;
        int orig = ((pcol >> 4) & 3) * 512 + (pcol >> 6) * 16 + (pcol & 15);
        if (g == 4) g_xrowp[pcol] = dWx0[orig];
        else {
            const float* s = (g == 0) ? b0 : (g == 1) ? b1 : (g == 2) ? b2 : b3;
            g_biasp[g * 2048 + pcol] = s[orig];
        }
    }
    if (i < B_SZ * U_SZ) { g_c0[i] = 0.f; g_c1[i] = 0.f; }
    if (i < B_SZ) g_xb[0][i] = dcin[i];
}

__global__ void final_kernel(float* __restrict__ out)
{
    int m = threadIdx.x;
    if (m < B_SZ) out[m * HORIZON + (HORIZON - 1)] = g_xb[HORIZON & 1][m];
}

extern "C" void kernel_launch(void* const* d_in, const int* in_sizes, int n_in,
                              void* d_out, int out_size)
{
    const float* enc  = (const float*)d_in[0];
    const float* dcin = (const float*)d_in[1];
    const float* eWx0 = (const float*)d_in[2];
    const float* eWh0 = (const float*)d_in[3];
    const float* eb0  = (const float*)d_in[4];
    const float* eWx1 = (const float*)d_in[5];
    const float* eWh1 = (const float*)d_in[6];
    const float* eb1  = (const float*)d_in[7];
    const float* dWx0 = (const float*)d_in[8];
    const float* dWh0 = (const float*)d_in[9];
    const float* db0  = (const float*)d_in[10];
    const float* dWx1 = (const float*)d_in[11];
    const float* dWh1 = (const float*)d_in[12];
    const float* db1  = (const float*)d_in[13];
    const float* Wd   = (const float*)d_in[14];
    const float* bd   = (const float*)d_in[15];
    float* out = (float*)d_out;

    cudaFuncSetAttribute(lstm_mma, cudaFuncAttributeMaxDynamicSharedMemorySize, NSTG * STAGE);

    __half *We0h, *We1h, *Wd0h, *Wd1h;
    __half *o0h, *xih, *h1h, *d0h, *zh;
    float *c0, *c1, *biasp, *xrowp, *xb;
    cudaGetSymbolAddress((void**)&We0h, g_We0h);
    cudaGetSymbolAddress((void**)&We1h, g_We1h);
    cudaGetSymbolAddress((void**)&Wd0h, g_Wd0h);
    cudaGetSymbolAddress((void**)&Wd1h, g_Wd1h);
    cudaGetSymbolAddress((void**)&o0h, g_o0h);
    cudaGetSymbolAddress((void**)&xih, g_xih);
    cudaGetSymbolAddress((void**)&h1h, g_h1h);
    cudaGetSymbolAddress((void**)&d0h, g_d0h);
    cudaGetSymbolAddress((void**)&zh, g_zh);
    cudaGetSymbolAddress((void**)&c0, g_c0);     cudaGetSymbolAddress((void**)&c1, g_c1);
    cudaGetSymbolAddress((void**)&biasp, g_biasp);
    cudaGetSymbolAddress((void**)&xrowp, g_xrowp);
    cudaGetSymbolAddress((void**)&xb, g_xb);

    auto mkjob = [&](const __half* a0hh, int nk0,
                     const __half* a1hh, int nk1,
                     const __half* whh, int T16,
                     const float* bp, float* cst, __half* oh) {
        Job j;
        j.a0h = a0hh; j.nk0 = nk0;
        j.a1h = a1hh; j.nk1 = nk1;
        j.wh = whh; j.T16 = T16;
        j.biasp = bp;
        j.xrowp = nullptr; j.xvec = nullptr; j.bdp = nullptr;
        j.youtprev = nullptr; j.xinit = nullptr;
        j.projWd = nullptr; j.xnext = nullptr;
        j.c = cst; j.outh = oh;
        return j;
    };

    // ---- preprocessing ----
    const int WTOT = (576 + 1024 + 512 + 1024) * 2048;
    prep_w<<<(WTOT + 255) / 256, 256>>>(eWx0, eWh0, eWx1, eWh1, dWh0, dWx1, dWh1);
    prep_misc<<<(T_ENC * B_SZ * 16 + 255) / 256, 256>>>(enc, dcin, eb0, eb1, db0, db1, dWx0);

    // ---- encoder: fused l0(s) + l1(s-1), s = 0..336 ----
    for (int s = 0; s <= T_ENC; ++s) {
        Job jobs[2];
        int nj = 0;
        if (s < T_ENC) {   // layer0 step s (T16=36: x2 | h32 | zero-pad2)
            const __half* hh = (s == 0) ? zh : o0h + (size_t)(s - 1) * SLOT_E;
            jobs[nj++] = mkjob(xih + (size_t)s * 8192, 2,
                               hh, 32, We0h, 36,
                               biasp + 0 * 2048, c0,
                               o0h + (size_t)s * SLOT_E);
        }
        if (s >= 1) {      // layer1 step s-1
            int t = s - 1;
            const __half* hh = (t == 0) ? zh : h1h + (size_t)(t & 1) * SLOT_E;
            jobs[nj++] = mkjob(o0h + (size_t)t * SLOT_E, 32,
                               hh, 32, We1h, 64,
                               biasp + 1 * 2048, c1,
                               h1h + (size_t)((t + 1) & 1) * SLOT_E);
        }
        dim3 grid(32, 4, nj);
        lstm_mma<<<grid, 256, NSTG * STAGE>>>(jobs[0], jobs[nj - 1]);
    }

    // ---- decoder ----
    for (int d = 0; d < HORIZON; ++d) {
        // layer 0 (K=512) + rank-1 x + bookkeeping
        {
            const __half* h0hh = (d == 0) ? o0h + (size_t)(T_ENC - 1) * SLOT_E
                                          : d0h + (size_t)(d & 1) * SLOT_E;
            Job j = mkjob(h0hh, 32, nullptr, 0,
                          Wd0h, 32, biasp + 2 * 2048, c0,
                          d0h + (size_t)((d & 1) ^ 1) * SLOT_E);
            j.xrowp = xrowp;
            j.xvec  = xb + (size_t)(d & 1) * B_SZ;
            j.bdp   = bd;
            j.youtprev = (d == 0) ? nullptr : out + (d - 1);
            j.xinit = xb + (size_t)((d + 1) & 1) * B_SZ;
            lstm_mma<<<dim3(32, 4, 1), 256, NSTG * STAGE>>>(j, j);
        }
        // layer 1 (K=1024) + fused projection
        {
            Job j = mkjob(d0h + (size_t)((d & 1) ^ 1) * SLOT_E, 32,
                          h1h + (size_t)(d & 1) * SLOT_E, 32,
                          Wd1h, 64, biasp + 3 * 2048, c1,
                          h1h + (size_t)((d + 1) & 1) * SLOT_E);
            j.projWd = Wd;
            j.xnext  = xb + (size_t)((d + 1) & 1) * B_SZ;
            lstm_mma<<<dim3(32, 4, 1), 256, NSTG * STAGE>>>(j, j);
        }
    }
    final_kernel<<<1, 256>>>(out);
}